// round 9
// baseline (speedup 1.0000x reference)
#include <cuda_runtime.h>
#include <cstddef>

#define BB 4
#define NN 8192
#define CC 128
#define SS 2048
#define KK 32

#define G   8            // CTAs per cluster (per batch), portable max
#define FTC 128          // threads per FPS CTA
#define PPC (NN / G)     // 1024 points per CTA
#define PTT (PPC / FTC)  // 8 points per thread
#define NP2 (PTT / 2)    // 4 packed pairs
#define WPC (FTC / 32)   // 4 warps per CTA
#define NKEYS (G * WPC)  // 32 warp keys per step (one per lane)

typedef unsigned long long u64;

__device__ int g_fps_idx[BB * SS];

// ---- packed f32x2 helpers (each half is an independent IEEE f32 rn op) ----
__device__ __forceinline__ u64 f2add(u64 a, u64 b) {
    u64 d; asm("add.rn.f32x2 %0, %1, %2;" : "=l"(d) : "l"(a), "l"(b)); return d;
}
__device__ __forceinline__ u64 f2mul(u64 a, u64 b) {
    u64 d; asm("mul.rn.f32x2 %0, %1, %2;" : "=l"(d) : "l"(a), "l"(b)); return d;
}
__device__ __forceinline__ u64 f2pack(float lo, float hi) {
    u64 d; asm("mov.b64 %0, {%1, %2};" : "=l"(d) : "f"(lo), "f"(hi)); return d;
}
__device__ __forceinline__ void f2unpack(u64 v, float& lo, float& hi) {
    asm("mov.b64 {%0, %1}, %2;" : "=f"(lo), "=f"(hi) : "l"(v));
}

__device__ __forceinline__ unsigned smem_u32(const void* p) {
    unsigned a;
    asm("{ .reg .u64 t; cvta.to.shared.u64 t, %1; cvt.u32.u64 %0, t; }" : "=r"(a) : "l"(p));
    return a;
}
__device__ __forceinline__ unsigned cluster_rank() {
    unsigned r; asm("mov.u32 %0, %%cluster_ctarank;" : "=r"(r)); return r;
}
__device__ __forceinline__ unsigned mapa_u32(unsigned laddr, unsigned rank) {
    unsigned r; asm("mapa.shared::cluster.u32 %0, %1, %2;" : "=r"(r) : "r"(laddr), "r"(rank));
    return r;
}
__device__ __forceinline__ void st_cluster_u64(unsigned addr, u64 v) {
    asm volatile("st.shared::cluster.b64 [%0], %1;" :: "r"(addr), "l"(v) : "memory");
}
// release-arrive: orders + flushes the preceding peer store (R6-proven path)
__device__ __forceinline__ void arrive_cluster(unsigned addr) {
    asm volatile("mbarrier.arrive.shared::cluster.b64 _, [%0];" :: "r"(addr) : "memory");
}
__device__ __forceinline__ void mbar_init(unsigned addr, unsigned cnt) {
    asm volatile("mbarrier.init.shared.b64 [%0], %1;" :: "r"(addr), "r"(cnt) : "memory");
}
// local volatile poll (29-cy LDS path)
__device__ __forceinline__ u64 lds_volatile_u64(unsigned addr) {
    u64 v;
    asm volatile("ld.volatile.shared.b64 %0, [%1];" : "=l"(v) : "r"(addr) : "memory");
    return v;
}
__device__ __forceinline__ void cluster_sync() {
    asm volatile("barrier.cluster.arrive.aligned;" ::: "memory");
    asm volatile("barrier.cluster.wait.aligned;" ::: "memory");
}

// ---------------------------------------------------------------------------
// FPS: 8-CTA cluster per batch, 128 threads/CTA, 8 pts/thread in registers.
// Packed f32x2 distance update (bit-exact to scalar unfused form).
// Sync: tagged mailbox + release-arrive-as-flush, poll-as-wait.
//   Writer: st.shared::cluster(key with embedded step tag) then
//   mbarrier.arrive.shared::cluster on the same peer — the release arrive
//   is what pushes the store out promptly (R7/R8 lesson: relaxed stores
//   with no release linger ~2000 cy).
//   Reader: polls its OWN slot with volatile LDS until the tag matches;
//   never waits on the mbarrier (no TRYWAIT wakeup on critical path). The
//   mbarrier still completes consistently each step (32 arrivals, no waiter).
// Double-buffered by parity; tags unique per step -> no stale match.
// ---------------------------------------------------------------------------
__global__ __launch_bounds__(FTC, 1) __cluster_dims__(G, 1, 1)
void fps_kernel(const float* __restrict__ xyz)
{
    const int b = blockIdx.x / G;
    const unsigned r = cluster_rank();
    const int t = threadIdx.x;
    const int lane = t & 31;
    const int w = t >> 5;

    extern __shared__ float4 sxyz[];          // NN float4 (x,y,z,0) -> LDS.128

    __shared__ __align__(8) u64 mbox[2][NKEYS];
    __shared__ __align__(8) u64 mbar[2];

    const float* base = xyz + (size_t)b * NN * 3;

    for (int i = t; i < NN; i += FTC) {
        sxyz[i] = make_float4(base[i * 3 + 0], base[i * 3 + 1], base[i * 3 + 2], 0.0f);
    }
    if (t < NKEYS) { mbox[0][t] = 0ull; mbox[1][t] = 0ull; }   // tag 0 unused
    if (t == 0) {
        mbar_init(smem_u32(&mbar[0]), NKEYS);
        mbar_init(smem_u32(&mbar[1]), NKEYS);
        if (r == 0) g_fps_idx[b * SS + 0] = 0;
    }
    __syncthreads();
    cluster_sync();   // tiles + mailboxes + mbarriers visible cluster-wide

    // pack this CTA's slice into registers
    const int gstart = (int)r * PPC + t * PTT;
    u64 pX[NP2], pY[NP2], pZ[NP2];
    float pd[PTT];
#pragma unroll
    for (int jp = 0; jp < NP2; jp++) {
        const int i0 = gstart + 2 * jp;
        const float4 a0 = sxyz[i0];
        const float4 a1 = sxyz[i0 + 1];
        pX[jp] = f2pack(a0.x, a1.x);
        pY[jp] = f2pack(a0.y, a1.y);
        pZ[jp] = f2pack(a0.z, a1.z);
        pd[2 * jp] = 1e10f;
        pd[2 * jp + 1] = 1e10f;
    }

    const unsigned mbox_l    = smem_u32(&mbox[0][0]);
    const unsigned mbar_l    = smem_u32(&mbar[0]);
    const unsigned my_slot_l = mbox_l + (unsigned)((r * WPC + w) * sizeof(u64));
    const unsigned bufstride = (unsigned)(sizeof(u64) * NKEYS);

    int far = 0;

    for (int step = 1; step < SS; ++step) {
        const unsigned buf = (unsigned)step & 1u;
        const unsigned tag = (unsigned)step & 0xFFFFu;

        const float4 c = sxyz[far];
        const u64 ncx = f2pack(-c.x, -c.x);
        const u64 ncy = f2pack(-c.y, -c.y);
        const u64 ncz = f2pack(-c.z, -c.z);

#pragma unroll
        for (int jp = 0; jp < NP2; jp++) {
            const u64 dx = f2add(pX[jp], ncx);
            const u64 dy = f2add(pY[jp], ncy);
            const u64 dz = f2add(pZ[jp], ncz);
            const u64 xx = f2mul(dx, dx);
            const u64 yy = f2mul(dy, dy);
            const u64 zz = f2mul(dz, dz);
            const u64 d  = f2add(f2add(xx, yy), zz);
            float dlo, dhi;
            f2unpack(d, dlo, dhi);
            pd[2 * jp]     = fminf(pd[2 * jp],     dlo);
            pd[2 * jp + 1] = fminf(pd[2 * jp + 1], dhi);
        }

        // per-thread max (tree) + first local index achieving it
        float m01[4];
#pragma unroll
        for (int j = 0; j < 4; j++) m01[j] = fmaxf(pd[2 * j], pd[2 * j + 1]);
        const float tv = fmaxf(fmaxf(m01[0], m01[1]), fmaxf(m01[2], m01[3]));

        int bj = PTT - 1;
#pragma unroll
        for (int j = PTT - 2; j >= 0; j--)
            if (pd[j] == tv) bj = j;
        const unsigned gi = (unsigned)(gstart + bj);

        // warp argmax: REDUX max on value bits (monotone, d >= 0),
        // then REDUX min on index among value-ties (= first-index tie-break)
        const unsigned vb = __float_as_uint(tv);
        const unsigned wm = __reduce_max_sync(0xffffffffu, vb);
        const unsigned wi = __reduce_min_sync(0xffffffffu, (vb == wm) ? gi : 0xffffffffu);

        // lanes 0..G-1: tagged key to peer 'lane', then release-arrive on the
        // SAME peer's mbarrier (flushes the store; nobody waits on the barrier)
        const u64 key = ((u64)wm << 32) | ((u64)tag << 16) | (u64)wi;
        if (lane < G) {
            const unsigned slot = my_slot_l + buf * bufstride;
            const unsigned bar  = mbar_l + buf * 8u;
            st_cluster_u64(mapa_u32(slot, (unsigned)lane), key);
            arrive_cluster(mapa_u32(bar, (unsigned)lane));
        }

        // poll own mailbox slot (LOCAL volatile LDS)
        const unsigned pa = mbox_l + buf * bufstride + (unsigned)lane * 8u;
        u64 k = lds_volatile_u64(pa);
        while (((unsigned)(k >> 16) & 0xFFFFu) != tag) k = lds_volatile_u64(pa);

        const unsigned hi = (unsigned)(k >> 32);
        const unsigned bm = __reduce_max_sync(0xffffffffu, hi);
        const unsigned fm = __reduce_min_sync(0xffffffffu,
                                              (hi == bm) ? ((unsigned)k & 0xFFFFu)
                                                         : 0xffffffffu);
        far = (int)fm;

        if (r == 0 && t == 0) g_fps_idx[b * SS + step] = far;
    }
}

// ---------------------------------------------------------------------------
// Fused ball query + grouping + affine + channel max (unchanged, bit-exact).
// ---------------------------------------------------------------------------
__global__ __launch_bounds__(128) void group_kernel(
    const float* __restrict__ xyz,
    const float* __restrict__ points,
    const float* __restrict__ alpha,
    const float* __restrict__ beta,
    float* __restrict__ out_xyz,
    float* __restrict__ out_pts)
{
    const int s = blockIdx.x;
    const int b = blockIdx.y;
    const int tid = threadIdx.x;

    __shared__ int   s_nbr[KK];
    __shared__ int   s_wc[4];
    __shared__ float s_q[3];

    const int fi = g_fps_idx[b * SS + s];
    const float* xb = xyz + (size_t)b * NN * 3;

    if (tid == 0) {
        s_q[0] = xb[fi * 3 + 0];
        s_q[1] = xb[fi * 3 + 1];
        s_q[2] = xb[fi * 3 + 2];
    }
    __syncthreads();

    const float qx = s_q[0], qy = s_q[1], qz = s_q[2];
    const float q2 = __fadd_rn(__fadd_rn(__fmul_rn(qx, qx), __fmul_rn(qy, qy)),
                               __fmul_rn(qz, qz));
    const float RR = 0.04f;   // f32(0.2 * 0.2)

    int cnt = 0;
    const int lane = tid & 31;
    const int w = tid >> 5;

    for (int base2 = 0; base2 < NN && cnt < KK; base2 += 128) {
        const int i = base2 + tid;
        const float xx = xb[i * 3 + 0];
        const float xy = xb[i * 3 + 1];
        const float xz = xb[i * 3 + 2];
        const float x2 = __fadd_rn(__fadd_rn(__fmul_rn(xx, xx), __fmul_rn(xy, xy)),
                                   __fmul_rn(xz, xz));
        const float dt = __fmaf_rn(qz, xz, __fmaf_rn(qy, xy, __fmul_rn(qx, xx)));
        const float sqr = __fsub_rn(__fadd_rn(q2, x2), __fmul_rn(2.0f, dt));
        const bool hit = (sqr <= RR);

        const unsigned m = __ballot_sync(0xffffffffu, hit);
        if (lane == 0) s_wc[w] = __popc(m);
        __syncthreads();

        int before = cnt;
        for (int ww = 0; ww < w; ww++) before += s_wc[ww];
        const int pos = before + __popc(m & ((1u << lane) - 1u));
        if (hit && pos < KK) s_nbr[pos] = i;
        const int tot = s_wc[0] + s_wc[1] + s_wc[2] + s_wc[3];
        __syncthreads();
        cnt += tot;   // uniform across block
    }

    const int cf = (cnt < KK) ? cnt : KK;
    if (tid >= cf && tid < KK) s_nbr[tid] = s_nbr[0];   // pad with first hit
    __syncthreads();

    if (tid < 3) out_xyz[((size_t)b * SS + s) * 3 + tid] = s_q[tid];

    const int c = tid;
    const float a  = alpha[c];
    const float bt = beta[c];
    const float* pb = points + (size_t)b * NN * CC;
    const float anc = pb[(size_t)fi * CC + c];

    float mx = -3.402823466e38f;
#pragma unroll 8
    for (int k = 0; k < KK; k++) {
        const float v = pb[(size_t)s_nbr[k] * CC + c];
        const float g = __fadd_rn(__fmul_rn(a, __fsub_rn(v, anc)), bt);
        mx = fmaxf(mx, g);
    }
    out_pts[((size_t)b * CC + c) * SS + s] = mx;
}

// ---------------------------------------------------------------------------
// Output layout: new_xyz (B,S,3) flat, then new_points (B,C,S) flat.
// ---------------------------------------------------------------------------
extern "C" void kernel_launch(void* const* d_in, const int* in_sizes, int n_in,
                              void* d_out, int out_size)
{
    const float* xyz    = (const float*)d_in[0];
    const float* points = (const float*)d_in[1];
    const float* alpha  = (const float*)d_in[2];
    const float* beta   = (const float*)d_in[3];

    float* out     = (float*)d_out;
    float* out_xyz = out;
    float* out_pts = out + (size_t)BB * SS * 3;

    cudaFuncSetAttribute(fps_kernel, cudaFuncAttributeMaxDynamicSharedMemorySize,
                         NN * (int)sizeof(float4));
    fps_kernel<<<BB * G, FTC, NN * sizeof(float4)>>>(xyz);
    group_kernel<<<dim3(SS, BB), 128>>>(xyz, points, alpha, beta, out_xyz, out_pts);
}

// round 11
// speedup vs baseline: 3.3947x; 3.3947x over previous
#include <cuda_runtime.h>
#include <cstddef>

#define BB 4
#define NN 8192
#define CC 128
#define SS 2048
#define KK 32

#define G   8            // CTAs per cluster (per batch), portable max
#define FTC 128          // threads per FPS CTA
#define PPC (NN / G)     // 1024 points per CTA
#define PTT (PPC / FTC)  // 8 points per thread
#define NP2 (PTT / 2)    // 4 packed pairs
#define WPC (FTC / 32)   // 4 warps per CTA
#define NKEYS (G * WPC)  // 32 warp keys per step (one per lane)

typedef unsigned long long u64;

__device__ int g_fps_idx[BB * SS];

// ---- packed f32x2 helpers (each half is an independent IEEE f32 rn op) ----
__device__ __forceinline__ u64 f2add(u64 a, u64 b) {
    u64 d; asm("add.rn.f32x2 %0, %1, %2;" : "=l"(d) : "l"(a), "l"(b)); return d;
}
__device__ __forceinline__ u64 f2mul(u64 a, u64 b) {
    u64 d; asm("mul.rn.f32x2 %0, %1, %2;" : "=l"(d) : "l"(a), "l"(b)); return d;
}
__device__ __forceinline__ u64 f2pack(float lo, float hi) {
    u64 d; asm("mov.b64 %0, {%1, %2};" : "=l"(d) : "f"(lo), "f"(hi)); return d;
}
__device__ __forceinline__ void f2unpack(u64 v, float& lo, float& hi) {
    asm("mov.b64 {%0, %1}, %2;" : "=f"(lo), "=f"(hi) : "l"(v));
}

__device__ __forceinline__ unsigned smem_u32(const void* p) {
    unsigned a;
    asm("{ .reg .u64 t; cvta.to.shared.u64 t, %1; cvt.u32.u64 %0, t; }" : "=r"(a) : "l"(p));
    return a;
}
__device__ __forceinline__ unsigned cluster_rank() {
    unsigned r; asm("mov.u32 %0, %%cluster_ctarank;" : "=r"(r)); return r;
}
__device__ __forceinline__ unsigned mapa_u32(unsigned laddr, unsigned rank) {
    unsigned r; asm("mapa.shared::cluster.u32 %0, %1, %2;" : "=r"(r) : "r"(laddr), "r"(rank));
    return r;
}
__device__ __forceinline__ void st_cluster_u64(unsigned addr, u64 v) {
    asm volatile("st.shared::cluster.b64 [%0], %1;" :: "r"(addr), "l"(v) : "memory");
}
__device__ __forceinline__ void arrive_cluster(unsigned addr) {
    asm volatile("mbarrier.arrive.shared::cluster.b64 _, [%0];" :: "r"(addr) : "memory");
}
__device__ __forceinline__ void mbar_init(unsigned addr, unsigned cnt) {
    asm volatile("mbarrier.init.shared.b64 [%0], %1;" :: "r"(addr), "r"(cnt) : "memory");
}
// HW-sleep TRYWAIT (R6-proven): no SMEM poll traffic while waiting, so
// incoming DSMEM stores land unimpeded (R7-R9 lesson).
__device__ __forceinline__ void mbar_wait_cluster(unsigned addr, unsigned parity) {
    unsigned done;
    asm volatile(
        "{\n\t.reg .pred p;\n\t"
        "mbarrier.try_wait.parity.acquire.cluster.shared::cta.b64 p, [%1], %2;\n\t"
        "selp.b32 %0, 1, 0, p;\n\t}"
        : "=r"(done) : "r"(addr), "r"(parity) : "memory");
    if (!done) {
        asm volatile(
            "{\n\t.reg .pred P1;\n\t"
            "W_%=:\n\t"
            "mbarrier.try_wait.parity.acquire.cluster.shared::cta.b64 P1, [%0], %1, 0x989680;\n\t"
            "@P1 bra.uni D_%=;\n\t"
            "bra.uni W_%=;\n\t"
            "D_%=:\n\t}"
            :: "r"(addr), "r"(parity) : "memory");
    }
}
__device__ __forceinline__ void cluster_sync() {
    asm volatile("barrier.cluster.arrive.aligned;" ::: "memory");
    asm volatile("barrier.cluster.wait.aligned;" ::: "memory");
}

// ---------------------------------------------------------------------------
// FPS: 8-CTA cluster per batch, 128 threads/CTA, 8 pts/thread in registers.
// Packed f32x2 distance update (bit-exact to scalar unfused form).
// R6 sync scheme exactly: warp REDUX (max value bits, then min index among
// value-ties = first-index tie-break); lanes 0..7 store the warp key to peer
// CTA 'lane' + release-arrive IN PARALLEL; all threads HW-sleep on the
// mbarrier (32 arrivals); every warp reduces the 32 mailbox keys.
// R11 change: xyz in shared as float4 -> centroid fetch is one LDS.128.
// ---------------------------------------------------------------------------
__global__ __launch_bounds__(FTC, 1) __cluster_dims__(G, 1, 1)
void fps_kernel(const float* __restrict__ xyz)
{
    const int b = blockIdx.x / G;
    const unsigned r = cluster_rank();
    const int t = threadIdx.x;
    const int lane = t & 31;
    const int w = t >> 5;

    extern __shared__ float4 sxyz[];          // NN float4 (x,y,z,0)

    __shared__ __align__(8) u64 mbox[2][NKEYS];
    __shared__ __align__(8) u64 mbar[2];

    const float* base = xyz + (size_t)b * NN * 3;

    for (int i = t; i < NN; i += FTC) {
        sxyz[i] = make_float4(base[i * 3 + 0], base[i * 3 + 1], base[i * 3 + 2], 0.0f);
    }
    if (t == 0) {
        mbar_init(smem_u32(&mbar[0]), NKEYS);
        mbar_init(smem_u32(&mbar[1]), NKEYS);
        if (r == 0) g_fps_idx[b * SS + 0] = 0;
    }
    __syncthreads();
    cluster_sync();   // mbarriers + shared tiles visible before any arrive

    // pack this CTA's slice into registers
    const int gstart = (int)r * PPC + t * PTT;
    u64 pX[NP2], pY[NP2], pZ[NP2];
    float pd[PTT];
#pragma unroll
    for (int jp = 0; jp < NP2; jp++) {
        const int i0 = gstart + 2 * jp;
        const float4 a0 = sxyz[i0];
        const float4 a1 = sxyz[i0 + 1];
        pX[jp] = f2pack(a0.x, a1.x);
        pY[jp] = f2pack(a0.y, a1.y);
        pZ[jp] = f2pack(a0.z, a1.z);
        pd[2 * jp] = 1e10f;
        pd[2 * jp + 1] = 1e10f;
    }

    const unsigned mbox_l    = smem_u32(&mbox[0][0]);
    const unsigned mbar_l    = smem_u32(&mbar[0]);
    const unsigned my_slot_l = mbox_l + (unsigned)((r * WPC + w) * sizeof(u64));
    const unsigned bufstride = (unsigned)(sizeof(u64) * NKEYS);

    int far = 0;
    unsigned ph[2] = {0u, 0u};

    for (int step = 1; step < SS; ++step) {
        const unsigned buf = (unsigned)step & 1u;

        const float4 c = sxyz[far];
        const u64 ncx = f2pack(-c.x, -c.x);
        const u64 ncy = f2pack(-c.y, -c.y);
        const u64 ncz = f2pack(-c.z, -c.z);

#pragma unroll
        for (int jp = 0; jp < NP2; jp++) {
            const u64 dx = f2add(pX[jp], ncx);
            const u64 dy = f2add(pY[jp], ncy);
            const u64 dz = f2add(pZ[jp], ncz);
            const u64 xx = f2mul(dx, dx);
            const u64 yy = f2mul(dy, dy);
            const u64 zz = f2mul(dz, dz);
            const u64 d  = f2add(f2add(xx, yy), zz);
            float dlo, dhi;
            f2unpack(d, dlo, dhi);
            pd[2 * jp]     = fminf(pd[2 * jp],     dlo);
            pd[2 * jp + 1] = fminf(pd[2 * jp + 1], dhi);
        }

        // per-thread max (tree) + first local index achieving it
        float m01[4];
#pragma unroll
        for (int j = 0; j < 4; j++) m01[j] = fmaxf(pd[2 * j], pd[2 * j + 1]);
        const float tv = fmaxf(fmaxf(m01[0], m01[1]), fmaxf(m01[2], m01[3]));

        int bj = PTT - 1;
#pragma unroll
        for (int j = PTT - 2; j >= 0; j--)
            if (pd[j] == tv) bj = j;
        const unsigned gi = (unsigned)(gstart + bj);

        // warp argmax: REDUX max on value bits (monotone, d >= 0),
        // then REDUX min on index among value-ties (= first-index tie-break)
        const unsigned vb = __float_as_uint(tv);
        const unsigned wm = __reduce_max_sync(0xffffffffu, vb);
        const unsigned wi = __reduce_min_sync(0xffffffffu, (vb == wm) ? gi : 0xffffffffu);

        // lanes 0..G-1 broadcast the (warp-uniform) key to peer 'lane' in parallel
        const u64 key = ((u64)wm << 32) | wi;
        if (lane < G) {
            st_cluster_u64(mapa_u32(my_slot_l + buf * bufstride, (unsigned)lane), key);
            arrive_cluster(mapa_u32(mbar_l + buf * 8u, (unsigned)lane));
        }

        // HW-sleep wait for all 32 warp keys, then reduce them per warp
        mbar_wait_cluster(mbar_l + buf * 8u, ph[buf]);
        ph[buf] ^= 1u;

        const u64 k = mbox[buf][lane];   // one key per lane
        const unsigned hi = (unsigned)(k >> 32);
        const unsigned bm = __reduce_max_sync(0xffffffffu, hi);
        const unsigned fm = __reduce_min_sync(0xffffffffu,
                                              (hi == bm) ? (unsigned)k : 0xffffffffu);
        far = (int)fm;

        if (r == 0 && t == 0) g_fps_idx[b * SS + step] = far;
    }
}

// ---------------------------------------------------------------------------
// Fused ball query + grouping + affine + channel max (unchanged, bit-exact).
// ---------------------------------------------------------------------------
__global__ __launch_bounds__(128) void group_kernel(
    const float* __restrict__ xyz,
    const float* __restrict__ points,
    const float* __restrict__ alpha,
    const float* __restrict__ beta,
    float* __restrict__ out_xyz,
    float* __restrict__ out_pts)
{
    const int s = blockIdx.x;
    const int b = blockIdx.y;
    const int tid = threadIdx.x;

    __shared__ int   s_nbr[KK];
    __shared__ int   s_wc[4];
    __shared__ float s_q[3];

    const int fi = g_fps_idx[b * SS + s];
    const float* xb = xyz + (size_t)b * NN * 3;

    if (tid == 0) {
        s_q[0] = xb[fi * 3 + 0];
        s_q[1] = xb[fi * 3 + 1];
        s_q[2] = xb[fi * 3 + 2];
    }
    __syncthreads();

    const float qx = s_q[0], qy = s_q[1], qz = s_q[2];
    const float q2 = __fadd_rn(__fadd_rn(__fmul_rn(qx, qx), __fmul_rn(qy, qy)),
                               __fmul_rn(qz, qz));
    const float RR = 0.04f;   // f32(0.2 * 0.2)

    int cnt = 0;
    const int lane = tid & 31;
    const int w = tid >> 5;

    for (int base2 = 0; base2 < NN && cnt < KK; base2 += 128) {
        const int i = base2 + tid;
        const float xx = xb[i * 3 + 0];
        const float xy = xb[i * 3 + 1];
        const float xz = xb[i * 3 + 2];
        const float x2 = __fadd_rn(__fadd_rn(__fmul_rn(xx, xx), __fmul_rn(xy, xy)),
                                   __fmul_rn(xz, xz));
        const float dt = __fmaf_rn(qz, xz, __fmaf_rn(qy, xy, __fmul_rn(qx, xx)));
        const float sqr = __fsub_rn(__fadd_rn(q2, x2), __fmul_rn(2.0f, dt));
        const bool hit = (sqr <= RR);

        const unsigned m = __ballot_sync(0xffffffffu, hit);
        if (lane == 0) s_wc[w] = __popc(m);
        __syncthreads();

        int before = cnt;
        for (int ww = 0; ww < w; ww++) before += s_wc[ww];
        const int pos = before + __popc(m & ((1u << lane) - 1u));
        if (hit && pos < KK) s_nbr[pos] = i;
        const int tot = s_wc[0] + s_wc[1] + s_wc[2] + s_wc[3];
        __syncthreads();
        cnt += tot;   // uniform across block
    }

    const int cf = (cnt < KK) ? cnt : KK;
    if (tid >= cf && tid < KK) s_nbr[tid] = s_nbr[0];   // pad with first hit
    __syncthreads();

    if (tid < 3) out_xyz[((size_t)b * SS + s) * 3 + tid] = s_q[tid];

    const int c = tid;
    const float a  = alpha[c];
    const float bt = beta[c];
    const float* pb = points + (size_t)b * NN * CC;
    const float anc = pb[(size_t)fi * CC + c];

    float mx = -3.402823466e38f;
#pragma unroll 8
    for (int k = 0; k < KK; k++) {
        const float v = pb[(size_t)s_nbr[k] * CC + c];
        const float g = __fadd_rn(__fmul_rn(a, __fsub_rn(v, anc)), bt);
        mx = fmaxf(mx, g);
    }
    out_pts[((size_t)b * CC + c) * SS + s] = mx;
}

// ---------------------------------------------------------------------------
// Output layout: new_xyz (B,S,3) flat, then new_points (B,C,S) flat.
// ---------------------------------------------------------------------------
extern "C" void kernel_launch(void* const* d_in, const int* in_sizes, int n_in,
                              void* d_out, int out_size)
{
    const float* xyz    = (const float*)d_in[0];
    const float* points = (const float*)d_in[1];
    const float* alpha  = (const float*)d_in[2];
    const float* beta   = (const float*)d_in[3];

    float* out     = (float*)d_out;
    float* out_xyz = out;
    float* out_pts = out + (size_t)BB * SS * 3;

    cudaFuncSetAttribute(fps_kernel, cudaFuncAttributeMaxDynamicSharedMemorySize,
                         NN * (int)sizeof(float4));
    fps_kernel<<<BB * G, FTC, NN * sizeof(float4)>>>(xyz);
    group_kernel<<<dim3(SS, BB), 128>>>(xyz, points, alpha, beta, out_xyz, out_pts);
}

// round 12
// speedup vs baseline: 3.3968x; 1.0006x over previous
#include <cuda_runtime.h>
#include <cstddef>

#define BB 4
#define NN 8192
#define CC 128
#define SS 2048
#define KK 32

#define G   8            // CTAs per cluster (per batch), portable max
#define FTC 128          // threads per FPS CTA
#define PPC (NN / G)     // 1024 points per CTA
#define PTT (PPC / FTC)  // 8 points per thread
#define NP2 (PTT / 2)    // 4 packed pairs
#define WPC (FTC / 32)   // 4 warps per CTA
#define NKEYS (G * WPC)  // 32 warp keys per step (one per lane)

#define GT 256           // group kernel threads
#define GW (GT / 32)     // 8 warps

typedef unsigned long long u64;

__device__ int g_fps_idx[BB * SS];

// ---- packed f32x2 helpers (each half is an independent IEEE f32 rn op) ----
__device__ __forceinline__ u64 f2add(u64 a, u64 b) {
    u64 d; asm("add.rn.f32x2 %0, %1, %2;" : "=l"(d) : "l"(a), "l"(b)); return d;
}
__device__ __forceinline__ u64 f2mul(u64 a, u64 b) {
    u64 d; asm("mul.rn.f32x2 %0, %1, %2;" : "=l"(d) : "l"(a), "l"(b)); return d;
}
__device__ __forceinline__ u64 f2pack(float lo, float hi) {
    u64 d; asm("mov.b64 %0, {%1, %2};" : "=l"(d) : "f"(lo), "f"(hi)); return d;
}
__device__ __forceinline__ void f2unpack(u64 v, float& lo, float& hi) {
    asm("mov.b64 {%0, %1}, %2;" : "=f"(lo), "=f"(hi) : "l"(v));
}

__device__ __forceinline__ unsigned smem_u32(const void* p) {
    unsigned a;
    asm("{ .reg .u64 t; cvta.to.shared.u64 t, %1; cvt.u32.u64 %0, t; }" : "=r"(a) : "l"(p));
    return a;
}
__device__ __forceinline__ unsigned cluster_rank() {
    unsigned r; asm("mov.u32 %0, %%cluster_ctarank;" : "=r"(r)); return r;
}
__device__ __forceinline__ unsigned mapa_u32(unsigned laddr, unsigned rank) {
    unsigned r; asm("mapa.shared::cluster.u32 %0, %1, %2;" : "=r"(r) : "r"(laddr), "r"(rank));
    return r;
}
__device__ __forceinline__ void st_cluster_u64(unsigned addr, u64 v) {
    asm volatile("st.shared::cluster.b64 [%0], %1;" :: "r"(addr), "l"(v) : "memory");
}
__device__ __forceinline__ void arrive_cluster(unsigned addr) {
    asm volatile("mbarrier.arrive.shared::cluster.b64 _, [%0];" :: "r"(addr) : "memory");
}
__device__ __forceinline__ void mbar_init(unsigned addr, unsigned cnt) {
    asm volatile("mbarrier.init.shared.b64 [%0], %1;" :: "r"(addr), "r"(cnt) : "memory");
}
// HW-sleep TRYWAIT (R6-proven): no SMEM poll traffic while waiting.
__device__ __forceinline__ void mbar_wait_cluster(unsigned addr, unsigned parity) {
    unsigned done;
    asm volatile(
        "{\n\t.reg .pred p;\n\t"
        "mbarrier.try_wait.parity.acquire.cluster.shared::cta.b64 p, [%1], %2;\n\t"
        "selp.b32 %0, 1, 0, p;\n\t}"
        : "=r"(done) : "r"(addr), "r"(parity) : "memory");
    if (!done) {
        asm volatile(
            "{\n\t.reg .pred P1;\n\t"
            "W_%=:\n\t"
            "mbarrier.try_wait.parity.acquire.cluster.shared::cta.b64 P1, [%0], %1, 0x989680;\n\t"
            "@P1 bra.uni D_%=;\n\t"
            "bra.uni W_%=;\n\t"
            "D_%=:\n\t}"
            :: "r"(addr), "r"(parity) : "memory");
    }
}
__device__ __forceinline__ void cluster_sync() {
    asm volatile("barrier.cluster.arrive.aligned;" ::: "memory");
    asm volatile("barrier.cluster.wait.aligned;" ::: "memory");
}

// ---------------------------------------------------------------------------
// FPS — byte-identical to R6 (best measured: 547 us / ~517 cy/step).
// ---------------------------------------------------------------------------
__global__ __launch_bounds__(FTC, 1) __cluster_dims__(G, 1, 1)
void fps_kernel(const float* __restrict__ xyz)
{
    const int b = blockIdx.x / G;
    const unsigned r = cluster_rank();
    const int t = threadIdx.x;
    const int lane = t & 31;
    const int w = t >> 5;

    extern __shared__ float sh[];
    float* sx = sh;
    float* sy = sh + NN;
    float* sz = sh + 2 * NN;

    __shared__ __align__(8) u64 mbox[2][NKEYS];
    __shared__ __align__(8) u64 mbar[2];

    const float* base = xyz + (size_t)b * NN * 3;

    for (int i = t; i < NN; i += FTC) {
        sx[i] = base[i * 3 + 0];
        sy[i] = base[i * 3 + 1];
        sz[i] = base[i * 3 + 2];
    }

    if (t == 0) {
        mbar_init(smem_u32(&mbar[0]), NKEYS);
        mbar_init(smem_u32(&mbar[1]), NKEYS);
        if (r == 0) g_fps_idx[b * SS + 0] = 0;
    }
    __syncthreads();
    cluster_sync();

    const int gstart = (int)r * PPC + t * PTT;
    u64 pX[NP2], pY[NP2], pZ[NP2];
    float pd[PTT];
#pragma unroll
    for (int jp = 0; jp < NP2; jp++) {
        const int i0 = gstart + 2 * jp;
        pX[jp] = f2pack(sx[i0], sx[i0 + 1]);
        pY[jp] = f2pack(sy[i0], sy[i0 + 1]);
        pZ[jp] = f2pack(sz[i0], sz[i0 + 1]);
        pd[2 * jp] = 1e10f;
        pd[2 * jp + 1] = 1e10f;
    }

    const unsigned mbox_l    = smem_u32(&mbox[0][0]);
    const unsigned mbar_l    = smem_u32(&mbar[0]);
    const unsigned my_slot_l = mbox_l + (unsigned)((r * WPC + w) * sizeof(u64));
    const unsigned bufstride = (unsigned)(sizeof(u64) * NKEYS);

    int far = 0;
    unsigned ph[2] = {0u, 0u};

    for (int step = 1; step < SS; ++step) {
        const unsigned buf = (unsigned)step & 1u;

        const float cx = sx[far];
        const float cy = sy[far];
        const float cz = sz[far];
        const u64 ncx = f2pack(-cx, -cx);
        const u64 ncy = f2pack(-cy, -cy);
        const u64 ncz = f2pack(-cz, -cz);

#pragma unroll
        for (int jp = 0; jp < NP2; jp++) {
            const u64 dx = f2add(pX[jp], ncx);
            const u64 dy = f2add(pY[jp], ncy);
            const u64 dz = f2add(pZ[jp], ncz);
            const u64 xx = f2mul(dx, dx);
            const u64 yy = f2mul(dy, dy);
            const u64 zz = f2mul(dz, dz);
            const u64 d  = f2add(f2add(xx, yy), zz);
            float dlo, dhi;
            f2unpack(d, dlo, dhi);
            pd[2 * jp]     = fminf(pd[2 * jp],     dlo);
            pd[2 * jp + 1] = fminf(pd[2 * jp + 1], dhi);
        }

        float m01[4];
#pragma unroll
        for (int j = 0; j < 4; j++) m01[j] = fmaxf(pd[2 * j], pd[2 * j + 1]);
        const float tv = fmaxf(fmaxf(m01[0], m01[1]), fmaxf(m01[2], m01[3]));

        int bj = PTT - 1;
#pragma unroll
        for (int j = PTT - 2; j >= 0; j--)
            if (pd[j] == tv) bj = j;
        const unsigned gi = (unsigned)(gstart + bj);

        const unsigned vb = __float_as_uint(tv);
        const unsigned wm = __reduce_max_sync(0xffffffffu, vb);
        const unsigned wi = __reduce_min_sync(0xffffffffu, (vb == wm) ? gi : 0xffffffffu);

        const u64 key = ((u64)wm << 32) | wi;
        if (lane < G) {
            st_cluster_u64(mapa_u32(my_slot_l + buf * bufstride, (unsigned)lane), key);
            arrive_cluster(mapa_u32(mbar_l + buf * 8u, (unsigned)lane));
        }

        mbar_wait_cluster(mbar_l + buf * 8u, ph[buf]);
        ph[buf] ^= 1u;

        const u64 k = mbox[buf][lane];
        const unsigned hi = (unsigned)(k >> 32);
        const unsigned bm = __reduce_max_sync(0xffffffffu, hi);
        const unsigned fm = __reduce_min_sync(0xffffffffu,
                                              (hi == bm) ? (unsigned)k : 0xffffffffu);
        far = (int)fm;

        if (r == 0 && t == 0) g_fps_idx[b * SS + step] = far;
    }
}

// ---------------------------------------------------------------------------
// Group: 256 threads/block.
// Phase 1: 256-pt chunks, ordered compaction, early exit (same neighbor set:
// compaction preserves ascending index order).
// Phase 2: K split in 2 halves of 16 across thread pairs (c, h); partial
// maxes combined via smem. max is order-invariant -> bit-exact.
// ---------------------------------------------------------------------------
__global__ __launch_bounds__(GT) void group_kernel(
    const float* __restrict__ xyz,
    const float* __restrict__ points,
    const float* __restrict__ alpha,
    const float* __restrict__ beta,
    float* __restrict__ out_xyz,
    float* __restrict__ out_pts)
{
    const int s = blockIdx.x;
    const int b = blockIdx.y;
    const int tid = threadIdx.x;

    __shared__ int   s_nbr[KK];
    __shared__ int   s_wc[GW];
    __shared__ float s_q[3];
    __shared__ float s_pm[2][CC];

    const int fi = g_fps_idx[b * SS + s];
    const float* xb = xyz + (size_t)b * NN * 3;

    if (tid == 0) {
        s_q[0] = xb[fi * 3 + 0];
        s_q[1] = xb[fi * 3 + 1];
        s_q[2] = xb[fi * 3 + 2];
    }
    __syncthreads();

    const float qx = s_q[0], qy = s_q[1], qz = s_q[2];
    const float q2 = __fadd_rn(__fadd_rn(__fmul_rn(qx, qx), __fmul_rn(qy, qy)),
                               __fmul_rn(qz, qz));
    const float RR = 0.04f;   // f32(0.2 * 0.2)

    int cnt = 0;
    const int lane = tid & 31;
    const int w = tid >> 5;

    for (int base2 = 0; base2 < NN && cnt < KK; base2 += GT) {
        const int i = base2 + tid;
        const float xx = xb[i * 3 + 0];
        const float xy = xb[i * 3 + 1];
        const float xz = xb[i * 3 + 2];
        const float x2 = __fadd_rn(__fadd_rn(__fmul_rn(xx, xx), __fmul_rn(xy, xy)),
                                   __fmul_rn(xz, xz));
        // GEMM-style fma-chain dot (k-order 0,1,2, acc starts at 0):
        const float dt = __fmaf_rn(qz, xz, __fmaf_rn(qy, xy, __fmul_rn(qx, xx)));
        const float sqr = __fsub_rn(__fadd_rn(q2, x2), __fmul_rn(2.0f, dt));
        const bool hit = (sqr <= RR);

        const unsigned m = __ballot_sync(0xffffffffu, hit);
        if (lane == 0) s_wc[w] = __popc(m);
        __syncthreads();

        int before = cnt;
#pragma unroll
        for (int ww = 0; ww < GW; ww++)
            if (ww < w) before += s_wc[ww];
        const int pos = before + __popc(m & ((1u << lane) - 1u));
        if (hit && pos < KK) s_nbr[pos] = i;
        int tot = 0;
#pragma unroll
        for (int ww = 0; ww < GW; ww++) tot += s_wc[ww];
        __syncthreads();
        cnt += tot;   // uniform across block
    }

    const int cf = (cnt < KK) ? cnt : KK;
    if (tid >= cf && tid < KK) s_nbr[tid] = s_nbr[0];   // pad with first hit
    __syncthreads();

    if (tid < 3) out_xyz[((size_t)b * SS + s) * 3 + tid] = s_q[tid];

    const int c = tid & (CC - 1);    // channel
    const int h = tid >> 7;          // K-half (0 or 1)
    const float a  = alpha[c];
    const float bt = beta[c];
    const float* pb = points + (size_t)b * NN * CC;
    const float anc = pb[(size_t)fi * CC + c];

    float mx = -3.402823466e38f;
#pragma unroll 8
    for (int k = h * (KK / 2); k < (h + 1) * (KK / 2); k++) {
        const float v = pb[(size_t)s_nbr[k] * CC + c];
        const float g = __fadd_rn(__fmul_rn(a, __fsub_rn(v, anc)), bt);
        mx = fmaxf(mx, g);
    }
    s_pm[h][c] = mx;
    __syncthreads();

    if (tid < CC)
        out_pts[((size_t)b * CC + tid) * SS + s] = fmaxf(s_pm[0][tid], s_pm[1][tid]);
}

// ---------------------------------------------------------------------------
// Output layout: new_xyz (B,S,3) flat, then new_points (B,C,S) flat.
// ---------------------------------------------------------------------------
extern "C" void kernel_launch(void* const* d_in, const int* in_sizes, int n_in,
                              void* d_out, int out_size)
{
    const float* xyz    = (const float*)d_in[0];
    const float* points = (const float*)d_in[1];
    const float* alpha  = (const float*)d_in[2];
    const float* beta   = (const float*)d_in[3];

    float* out     = (float*)d_out;
    float* out_xyz = out;
    float* out_pts = out + (size_t)BB * SS * 3;

    cudaFuncSetAttribute(fps_kernel, cudaFuncAttributeMaxDynamicSharedMemorySize,
                         3 * NN * (int)sizeof(float));
    fps_kernel<<<BB * G, FTC, 3 * NN * sizeof(float)>>>(xyz);
    group_kernel<<<dim3(SS, BB), GT>>>(xyz, points, alpha, beta, out_xyz, out_pts);
}